// round 9
// baseline (speedup 1.0000x reference)
#include <cuda_runtime.h>
#include <mma.h>
using namespace nvcuda;

#define BATCH   8
#define NP1     1024
#define DP1     128
#define NLAYER  4
#define NHEAD   8
#define NTOK    1023
#define DSMALL  127

#define LD128   132
#define LD64    68
#define LD32    36

// tr: buf[128][132] (G then Q) + Ps[128][36] + Ts[128][36]
#define TR_SMEM   ((DP1 * LD128 + 2 * DP1 * LD32) * 4)          // 104448 -> 2/SM
// update: Gs[128][132] + Ra/Rb/Gl [128][68]x3
#define UPD_SMEM  ((DP1 * LD128 + 3 * DP1 * LD64) * 4)          // 172032
// gram: Zs[64][132] + Cs[128][132]
#define GRAM_SMEM ((64 * LD128 + DP1 * LD128) * 4)              // 101376
// final: Zs[128][132] + Es[128][132]
#define FIN_SMEM  ((2 * DP1 * LD128) * 4)                       // 135168

// ---------------------------------------------------------------------------
// g_PB[l][h][a][b] = Pfull[b][a]; g_QT[l][h][k][i] = Qfull[i][k]
// g_G[gp][b] : Gram ping-pong (layer l reads gp=l&1, update writes gp^1)
// g_R[p][b]  : R ping-pong (R[p^1] zeroed by update of layer p)
// g_W[p][b]  : W = M^T ping-pong (I included)
// ---------------------------------------------------------------------------
__device__ __align__(16) float g_PB[NLAYER][NHEAD][DP1][DP1];
__device__ __align__(16) float g_QT[NLAYER][NHEAD][DP1][DP1];
__device__ __align__(16) float g_G [2][BATCH][DP1][DP1];
__device__ __align__(16) float g_R [2][BATCH][DP1][DP1];
__device__ __align__(16) float g_W [2][BATCH][DP1][DP1];

__device__ __forceinline__ float4 tf32x4(float4 v) {
    v.x = wmma::__float_to_tf32(v.x);  v.y = wmma::__float_to_tf32(v.y);
    v.z = wmma::__float_to_tf32(v.z);  v.w = wmma::__float_to_tf32(v.w);
    return v;
}

// ---------------------------------------------------------------------------
// pad params + init state, one launch. grid 2048 x 256.
// ---------------------------------------------------------------------------
__global__ void padinit_kernel(const float* __restrict__ allparam) {
    int idx = blockIdx.x * blockDim.x + threadIdx.x;   // < 524288
    {
        int bb = idx & 127;
        int a  = (idx >> 7) & 127;
        int h  = (idx >> 14) & 7;
        int l  = idx >> 17;
        float pv = 0.0f, qv = 0.0f;
        if (bb < DSMALL && a < DSMALL) {
            const float* base = allparam
                + ((((size_t)l * NHEAD + h) * 2 + 0) * DSMALL + bb) * DSMALL + a;
            pv = base[0];
            qv = base[DSMALL * DSMALL];
        }
        if (bb == DSMALL && a == DSMALL) pv = 1.0f;
        g_PB[l][h][a][bb] = pv;
        g_QT[l][h][a][bb] = qv;
    }
    if (idx < BATCH * DP1 * DP1) {
        int j = idx & 127, i = (idx >> 7) & 127, b = idx >> 14;
        g_G[0][b][i][j] = 0.0f;
        g_R[0][b][i][j] = 0.0f;
        g_W[0][b][i][j] = (i == j) ? 1.0f : 0.0f;
    }
}

// ---------------------------------------------------------------------------
// Gram (tf32 wmma): G[0][b] += Zslab^T Zslab, rows [s*64, s*64+64) ∩ [0,1023)
// grid (8,16), 512 thr.
// ---------------------------------------------------------------------------
__global__ __launch_bounds__(512)
void gram_kernel(const float* __restrict__ Z) {
    extern __shared__ __align__(16) float dsm[];
    float* Zs = dsm;                 // [64][132]
    float* Cs = dsm + 64 * LD128;    // [128][132]

    const int b = blockIdx.x, s = blockIdx.y;
    const int tid = threadIdx.x;
    const int w = tid >> 5;
    const int rw = (w & 7) * 16;
    const int jt = (w >> 3) * 64;

    const float* Zb = Z + (size_t)b * NP1 * DP1;
    const int m0 = s * 64;

#pragma unroll
    for (int q = 0; q < 4; q++) {
        int f = tid + q * 512;
        int row = f >> 5, c4 = (f & 31) * 4;
        float4 v = make_float4(0.f, 0.f, 0.f, 0.f);
        if (m0 + row < NTOK)
            v = tf32x4(*(const float4*)&Zb[(size_t)(m0 + row) * DP1 + c4]);
        *(float4*)&Zs[row * LD128 + c4] = v;
    }
    __syncthreads();

    wmma::fragment<wmma::accumulator, 16, 16, 8, float> c[4];
#pragma unroll
    for (int j = 0; j < 4; j++) wmma::fill_fragment(c[j], 0.0f);

#pragma unroll
    for (int k0 = 0; k0 < 64; k0 += 8) {
        wmma::fragment<wmma::matrix_a, 16, 16, 8, wmma::precision::tf32,
                       wmma::col_major> a;
        wmma::load_matrix_sync(a, Zs + k0 * LD128 + rw, LD128);
#pragma unroll
        for (int j = 0; j < 4; j++) {
            wmma::fragment<wmma::matrix_b, 16, 16, 8, wmma::precision::tf32,
                           wmma::row_major> bf;
            wmma::load_matrix_sync(bf, Zs + k0 * LD128 + jt + j * 16, LD128);
            wmma::mma_sync(c[j], a, bf, c[j]);
        }
    }
#pragma unroll
    for (int j = 0; j < 4; j++)
        wmma::store_matrix_sync(Cs + rw * LD128 + jt + j * 16, c[j], LD128,
                                wmma::mem_row_major);
    __syncthreads();

    float* Gb = &g_G[0][b][0][0];
#pragma unroll
    for (int q = 0; q < 8; q++) {
        int f = tid + q * 512;
        int row = f >> 5, c4 = (f & 31) * 4;
        float4 v = *(const float4*)&Cs[row * LD128 + c4];
        float* dst = &Gb[row * DP1 + c4];
        atomicAdd(dst + 0, v.x);
        atomicAdd(dst + 1, v.y);
        atomicAdd(dst + 2, v.z);
        atomicAdd(dst + 3, v.w);
    }
}

// ---------------------------------------------------------------------------
// Fused TR. Block (b, h, s): cols [s*32, s*32+32). 256 thr = 8 warps.
// smem 104KB -> 2 blocks/SM (grid 256 on 148 SMs).
//   stage G -> buf; Phase1 Ts = G@P_slice; restage Q -> buf;
//   Phase2 C = Q@Ts; atomicAdd R[p][b][:, slice] += C/N.
// ---------------------------------------------------------------------------
__global__ __launch_bounds__(256, 2)
void tr_kernel(int layer, int p) {
    extern __shared__ __align__(16) float dsm[];
    float* buf = dsm;                       // [128][132]  G then Q
    float* Ps  = dsm + DP1 * LD128;         // [128][36]
    float* Ts  = Ps + DP1 * LD32;           // [128][36]

    const int b = blockIdx.x, h = blockIdx.y, s = blockIdx.z;
    const int c0 = s * 32;
    const int tid = threadIdx.x;
    const int w = tid >> 5;
    const int rw = w * 16;

    const float* Gb = &g_G[p][b][0][0];
    const float* PB = &g_PB[layer][h][0][0];
    const float* QT = &g_QT[layer][h][0][0];

    // stage G + P slice
#pragma unroll
    for (int q = 0; q < 16; q++) {
        int f = tid + q * 256;
        int row = f >> 5, c4 = (f & 31) * 4;
        *(float4*)&buf[row * LD128 + c4] =
            tf32x4(*(const float4*)&Gb[row * DP1 + c4]);
    }
#pragma unroll
    for (int q = 0; q < 4; q++) {
        int f = tid + q * 256;
        int row = f >> 3, c4 = (f & 7) * 4;
        *(float4*)&Ps[row * LD32 + c4] =
            tf32x4(*(const float4*)&PB[row * DP1 + c0 + c4]);
    }
    __syncthreads();

    // Phase 1: Ts = G @ Ps (warp w: rows rw..rw+16, cols 0..32)
    wmma::fragment<wmma::accumulator, 16, 16, 8, float> c0f, c1f;
    wmma::fill_fragment(c0f, 0.0f);
    wmma::fill_fragment(c1f, 0.0f);
#pragma unroll
    for (int k0 = 0; k0 < DP1; k0 += 8) {
        wmma::fragment<wmma::matrix_a, 16, 16, 8, wmma::precision::tf32,
                       wmma::row_major> a;
        wmma::load_matrix_sync(a, buf + rw * LD128 + k0, LD128);
        wmma::fragment<wmma::matrix_b, 16, 16, 8, wmma::precision::tf32,
                       wmma::row_major> b0, b1;
        wmma::load_matrix_sync(b0, Ts /*dummy avoid*/ == Ts ? Ps + k0 * LD32 : Ps, LD32);
        wmma::load_matrix_sync(b1, Ps + k0 * LD32 + 16, LD32);
        wmma::mma_sync(c0f, a, b0, c0f);
        wmma::mma_sync(c1f, a, b1, c1f);
    }
#pragma unroll
    for (int t = 0; t < c0f.num_elements; t++) {
        c0f.x[t] = wmma::__float_to_tf32(c0f.x[t]);
        c1f.x[t] = wmma::__float_to_tf32(c1f.x[t]);
    }
    wmma::store_matrix_sync(Ts + rw * LD32, c0f, LD32, wmma::mem_row_major);
    wmma::store_matrix_sync(Ts + rw * LD32 + 16, c1f, LD32, wmma::mem_row_major);
    __syncthreads();

    // restage Q over G
#pragma unroll
    for (int q = 0; q < 16; q++) {
        int f = tid + q * 256;
        int row = f >> 5, c4 = (f & 31) * 4;
        *(float4*)&buf[row * LD128 + c4] =
            tf32x4(*(const float4*)&QT[row * DP1 + c4]);
    }
    __syncthreads();

    // Phase 2: C = Q @ Ts
    wmma::fill_fragment(c0f, 0.0f);
    wmma::fill_fragment(c1f, 0.0f);
#pragma unroll
    for (int k0 = 0; k0 < DP1; k0 += 8) {
        wmma::fragment<wmma::matrix_a, 16, 16, 8, wmma::precision::tf32,
                       wmma::col_major> a;
        wmma::load_matrix_sync(a, buf + k0 * LD128 + rw, LD128);
        wmma::fragment<wmma::matrix_b, 16, 16, 8, wmma::precision::tf32,
                       wmma::row_major> b0, b1;
        wmma::load_matrix_sync(b0, Ts + k0 * LD32, LD32);
        wmma::load_matrix_sync(b1, Ts + k0 * LD32 + 16, LD32);
        wmma::mma_sync(c0f, a, b0, c0f);
        wmma::mma_sync(c1f, a, b1, c1f);
    }
    __syncthreads();   // Ts reads done; Ps dead since phase 1
    wmma::store_matrix_sync(Ps + rw * LD32, c0f, LD32, wmma::mem_row_major);
    wmma::store_matrix_sync(Ps + rw * LD32 + 16, c1f, LD32, wmma::mem_row_major);
    __syncthreads();

    const float invN = 1.0f / (float)NTOK;
    float* Rb = &g_R[p][b][0][0];
#pragma unroll
    for (int q = 0; q < 4; q++) {
        int f = tid + q * 256;
        int row = f >> 3, c4 = (f & 7) * 4;
        float4 v = *(const float4*)&Ps[row * LD32 + c4];
        float* dst = &Rb[row * DP1 + c0 + c4];
        atomicAdd(dst + 0, v.x * invN);
        atomicAdd(dst + 1, v.y * invN);
        atomicAdd(dst + 2, v.z * invN);
        atomicAdd(dst + 3, v.w * invN);
    }
}

// ---------------------------------------------------------------------------
// update: merged c1+c2.
//   G' tile (rt,ct): Gt_loc[:,ct] = G[:,ct] + G@R[:,ct]  (tf32 wmma)
//                    G'[rt,ct] = Gt_loc[rt,:] + R^T[rt,:]@Gt_loc
//   W  tile (rt,ct): W'[rt,ct] = W[rt,ct] + R^T[rt,:]@W[:,ct]  (fp32 SIMT)
// grid (8, last?4:8), 512 thr. d<4 -> G' tiles (skipped when last), else W.
// Also zeroes g_R[p^1] (non-last).
// ---------------------------------------------------------------------------
__global__ __launch_bounds__(512)
void update_kernel(int p, int last) {
    extern __shared__ __align__(16) float dsm[];
    const int b = blockIdx.x;
    const int d = blockIdx.y;
    const int tid = threadIdx.x;
    const int w = tid >> 5;

    const float* Rp = &g_R[p][b][0][0];
    const bool isW = last ? true : (d >= 4);
    const int td = last ? d : (isW ? d - 4 : d);
    const int r0 = (td >> 1) * 64, c0 = (td & 1) * 64;

    if (!isW) {
        float* Gs = dsm;                       // [128][132]
        float* Ra = dsm + DP1 * LD128;         // [128][68]  R[:, c0..]
        float* Rb = Ra + DP1 * LD64;           // [128][68]  R[:, r0..]
        float* Gl = Rb + DP1 * LD64;           // [128][68]  Gt_local
        const float* Gp = &g_G[p][b][0][0];

#pragma unroll
        for (int q = 0; q < 8; q++) {
            int f = tid + q * 512;
            int row = f >> 5, c4 = (f & 31) * 4;
            *(float4*)&Gs[row * LD128 + c4] =
                tf32x4(*(const float4*)&Gp[row * DP1 + c4]);
        }
#pragma unroll
        for (int q = 0; q < 4; q++) {
            int f = tid + q * 512;
            int row = f >> 4, c4 = (f & 15) * 4;
            *(float4*)&Ra[row * LD64 + c4] =
                tf32x4(*(const float4*)&Rp[row * DP1 + c0 + c4]);
            *(float4*)&Rb[row * LD64 + c4] =
                tf32x4(*(const float4*)&Rp[row * DP1 + r0 + c4]);
        }
        __syncthreads();

        // GEMM1: Gl = G @ Ra  (warp w: rows (w&7)*16, cols (w>>3)*32)
        {
            const int rw = (w & 7) * 16, jt = (w >> 3) * 32;
            wmma::fragment<wmma::accumulator, 16, 16, 8, float> c0f, c1f;
            wmma::fill_fragment(c0f, 0.0f);
            wmma::fill_fragment(c1f, 0.0f);
#pragma unroll
            for (int k0 = 0; k0 < DP1; k0 += 8) {
                wmma::fragment<wmma::matrix_a, 16, 16, 8, wmma::precision::tf32,
                               wmma::row_major> a;
                wmma::load_matrix_sync(a, Gs + rw * LD128 + k0, LD128);
                wmma::fragment<wmma::matrix_b, 16, 16, 8, wmma::precision::tf32,
                               wmma::row_major> b0, b1;
                wmma::load_matrix_sync(b0, Ra + k0 * LD64 + jt, LD64);
                wmma::load_matrix_sync(b1, Ra + k0 * LD64 + jt + 16, LD64);
                wmma::mma_sync(c0f, a, b0, c0f);
                wmma::mma_sync(c1f, a, b1, c1f);
            }
            wmma::store_matrix_sync(Gl + rw * LD64 + jt, c0f, LD64,
                                    wmma::mem_row_major);
            wmma::store_matrix_sync(Gl + rw * LD64 + jt + 16, c1f, LD64,
                                    wmma::mem_row_major);
        }
        __syncthreads();

        // Gl = round(Gl + G[:, c0..])
#pragma unroll
        for (int q = 0; q < 4; q++) {
            int f = tid + q * 512;
            int row = f >> 4, c4 = (f & 15) * 4;
            float4 v = *(const float4*)&Gl[row * LD64 + c4];
            float4 g = *(const float4*)&Gs[row * LD128 + c0 + c4];
            v.x += g.x; v.y += g.y; v.z += g.z; v.w += g.w;
            *(float4*)&Gl[row * LD64 + c4] = tf32x4(v);
        }
        __syncthreads();

        // GEMM2: S = R^T[rt band] @ Gl  (64x64; warp w: i0=(w&3)*16, j0=(w>>2)*16)
        {
            const int i0 = (w & 3) * 16, j0 = (w >> 2) * 16;
            wmma::fragment<wmma::accumulator, 16, 16, 8, float> cf;
            wmma::fill_fragment(cf, 0.0f);
#pragma unroll
            for (int k0 = 0; k0 < DP1; k0 += 8) {
                wmma::fragment<wmma::matrix_a, 16, 16, 8, wmma::precision::tf32,
                               wmma::col_major> a;
                wmma::load_matrix_sync(a, Rb + k0 * LD64 + i0, LD64);
                wmma::fragment<wmma::matrix_b, 16, 16, 8, wmma::precision::tf32,
                               wmma::row_major> bf;
                wmma::load_matrix_sync(bf, Gl + k0 * LD64 + j0, LD64);
                wmma::mma_sync(cf, a, bf, cf);
            }
            // store S into Ra (dead), 64 rows x LD64
            wmma::store_matrix_sync(Ra + i0 * LD64 + j0, cf, LD64,
                                    wmma::mem_row_major);
        }
        __syncthreads();

        // G'[r0+i][c0+j] = Gl[r0+i][j] + S[i][j]
        float* Gn = &g_G[p ^ 1][b][0][0];
#pragma unroll
        for (int q = 0; q < 2; q++) {
            int f = tid + q * 512;              // 0..1023 f4 (64x64/4)
            int row = f >> 4, c4 = (f & 15) * 4;
            float4 sv = *(const float4*)&Ra[row * LD64 + c4];
            float4 bv = *(const float4*)&Gl[(r0 + row) * LD64 + c4];
            *(float4*)&Gn[(r0 + row) * DP1 + c0 + c4] =
                make_float4(bv.x + sv.x, bv.y + sv.y, bv.z + sv.z, bv.w + sv.w);
        }
    } else {
        // W tile, fp32 SIMT
        float* Wc = dsm;                       // [128][68]  W[:, c0..]
        float* Rr = dsm + DP1 * LD64;          // [128][68]  R[:, r0..]
        const float* Wp = &g_W[p][b][0][0];

#pragma unroll
        for (int q = 0; q < 4; q++) {
            int f = tid + q * 512;
            int row = f >> 4, c4 = (f & 15) * 4;
            *(float4*)&Wc[row * LD64 + c4] =
                *(const float4*)&Wp[row * DP1 + c0 + c4];
            *(float4*)&Rr[row * LD64 + c4] =
                *(const float4*)&Rp[row * DP1 + r0 + c4];
        }
        __syncthreads();

        const int tx = tid & 15, ty = tid >> 4;   // cols tx*4, rows ty*2
        float acc[2][4] = {{0.f,0.f,0.f,0.f},{0.f,0.f,0.f,0.f}};
#pragma unroll 8
        for (int k = 0; k < DP1; k++) {
            float a0 = Rr[k * LD64 + ty * 2];
            float a1 = Rr[k * LD64 + ty * 2 + 1];
            float4 b4 = *(const float4*)&Wc[k * LD64 + tx * 4];
            acc[0][0] = fmaf(a0, b4.x, acc[0][0]);
            acc[0][1] = fmaf(a0, b4.y, acc[0][1]);
            acc[0][2] = fmaf(a0, b4.z, acc[0][2]);
            acc[0][3] = fmaf(a0, b4.w, acc[0][3]);
            acc[1][0] = fmaf(a1, b4.x, acc[1][0]);
            acc[1][1] = fmaf(a1, b4.y, acc[1][1]);
            acc[1][2] = fmaf(a1, b4.z, acc[1][2]);
            acc[1][3] = fmaf(a1, b4.w, acc[1][3]);
        }
        float* Wn = &g_W[p ^ 1][b][0][0];
#pragma unroll
        for (int i = 0; i < 2; i++) {
            int row = r0 + ty * 2 + i;
            float4 base = *(const float4*)&Wc[row * LD64 + tx * 4];
            *(float4*)&Wn[row * DP1 + c0 + tx * 4] =
                make_float4(base.x + acc[i][0], base.y + acc[i][1],
                            base.z + acc[i][2], base.w + acc[i][3]);
        }
    }

    // zero next-parity R (non-last): 8 blocks/b x 2048 floats = 512 f4 each
    if (!last) {
        float* Rn = &g_R[p ^ 1][b][0][0];
        int f = d * 512 + tid;                // 0..4095 f4 across 8 blocks
        *(float4*)&Rn[f * 4] = make_float4(0.f, 0.f, 0.f, 0.f);
    }
}

// ---------------------------------------------------------------------------
// Final (tf32 wmma on correction): Zout = Zin + Zin @ E^T, E = W[0] - I.
// grid (8,8), 512 thr.
// ---------------------------------------------------------------------------
__global__ __launch_bounds__(512)
void final_kernel(const float* __restrict__ Zin, float* __restrict__ Zout) {
    extern __shared__ __align__(16) float dsm[];
    float* Zs = dsm;                 // [128][132]
    float* Es = dsm + DP1 * LD128;   // [128][132]

    const int b = blockIdx.x, rt = blockIdx.y;
    const int n0 = rt * 128;
    const int tid = threadIdx.x;
    const int w = tid >> 5;
    const int rw = (w & 7) * 16;
    const int jt = (w >> 3) * 64;

    const float* Zb = Zin + (size_t)b * NP1 * DP1;
    float* Zo = Zout + (size_t)b * NP1 * DP1;
    const float* Wb = &g_W[0][b][0][0];

#pragma unroll
    for (int q = 0; q < 8; q++) {
        int f = tid + q * 512;
        int row = f >> 5, c4 = (f & 31) * 4;
        *(float4*)&Zs[row * LD128 + c4] =
            tf32x4(*(const float4*)&Zb[(size_t)(n0 + row) * DP1 + c4]);
        float4 e = *(const float4*)&Wb[row * DP1 + c4];
        if (row >= c4 && row < c4 + 4) {
            if (row == c4)          e.x -= 1.0f;
            else if (row == c4 + 1) e.y -= 1.0f;
            else if (row == c4 + 2) e.z -= 1.0f;
            else                    e.w -= 1.0f;
        }
        *(float4*)&Es[row * LD128 + c4] = tf32x4(e);
    }
    __syncthreads();

    wmma::fragment<wmma::accumulator, 16, 16, 8, float> c[4];
#pragma unroll
    for (int j = 0; j < 4; j++) wmma::fill_fragment(c[j], 0.0f);

#pragma unroll
    for (int k0 = 0; k0 < DP1; k0 += 8) {
        wmma::fragment<wmma::matrix_a, 16, 16, 8, wmma::precision::tf32,
                       wmma::row_major> a;
        wmma::load_matrix_sync(a, Zs + rw * LD128 + k0, LD128);
#pragma unroll
        for (int j = 0; j < 4; j++) {
            wmma::fragment<wmma::matrix_b, 16, 16, 8, wmma::precision::tf32,
                           wmma::col_major> bf;
            wmma::load_matrix_sync(bf, Es + (jt + j * 16) * LD128 + k0, LD128);
            wmma::mma_sync(c[j], a, bf, c[j]);
        }
    }
    __syncthreads();
#pragma unroll
    for (int j = 0; j < 4; j++)
        wmma::store_matrix_sync(Zs + rw * LD128 + jt + j * 16, c[j], LD128,
                                wmma::mem_row_major);
    __syncthreads();

#pragma unroll
    for (int q = 0; q < 8; q++) {
        int f = tid + q * 512;
        int row = f >> 5, c4 = (f & 31) * 4;
        size_t off = (size_t)(n0 + row) * DP1 + c4;
        float4 z = *(const float4*)&Zb[off];
        float4 cc = *(const float4*)&Zs[row * LD128 + c4];
        *(float4*)&Zo[off] =
            make_float4(z.x + cc.x, z.y + cc.y, z.z + cc.z, z.w + cc.w);
    }
}

// ---------------------------------------------------------------------------
extern "C" void kernel_launch(void* const* d_in, const int* in_sizes, int n_in,
                              void* d_out, int out_size) {
    const float* Z_in     = (const float*)d_in[0];
    const float* allparam = (const float*)d_in[1];
    float* Z_out = (float*)d_out;

    cudaFuncSetAttribute(tr_kernel,
                         cudaFuncAttributeMaxDynamicSharedMemorySize, TR_SMEM);
    cudaFuncSetAttribute(update_kernel,
                         cudaFuncAttributeMaxDynamicSharedMemorySize, UPD_SMEM);
    cudaFuncSetAttribute(gram_kernel,
                         cudaFuncAttributeMaxDynamicSharedMemorySize, GRAM_SMEM);
    cudaFuncSetAttribute(final_kernel,
                         cudaFuncAttributeMaxDynamicSharedMemorySize, FIN_SMEM);

    padinit_kernel<<<2048, 256>>>(allparam);
    gram_kernel<<<dim3(BATCH, 16), 512, GRAM_SMEM>>>(Z_in);

    for (int l = 0; l < NLAYER; l++) {
        int p = l & 1;
        int last = (l == NLAYER - 1) ? 1 : 0;
        tr_kernel<<<dim3(BATCH, NHEAD, 4), 256, TR_SMEM>>>(l, p);
        update_kernel<<<dim3(BATCH, last ? 4 : 8), 512, UPD_SMEM>>>(p, last);
    }

    final_kernel<<<dim3(BATCH, 8), 512, FIN_SMEM>>>(Z_in, Z_out);
}

// round 10
// speedup vs baseline: 1.6697x; 1.6697x over previous
#include <cuda_runtime.h>
#include <mma.h>
using namespace nvcuda;

#define BATCH   8
#define NP1     1024
#define DP1     128
#define NLAYER  4
#define NHEAD   8
#define NTOK    1023
#define DSMALL  127

#define LD128   132     // padded ld for 128-col tf32 operand
#define LD64    68      // padded ld for 64-col operand

// tr: Gs[128][132] + Qs[128][132] + Ps[128][68] + Ts[128][68]
#define TR_SMEM   ((2 * DP1 * LD128 + 2 * DP1 * LD64) * 4)       // 204800
// gram: Zs[64][132] + Cs[128][132]
#define GRAM_SMEM ((64 * LD128 + DP1 * LD128) * 4)               // 101376
// final: Zs[128][132] + Es[128][132]
#define FIN_SMEM  ((2 * DP1 * LD128) * 4)                        // 135168

// ---------------------------------------------------------------------------
// g_PB[l][h][a][b] = Pfull[b][a]   (P^T, padded; corner Pfull[127][127]=1)
// g_QT[l][h][k][i] = Qfull[i][k]   (Q^T, zero padded)
// g_G [b]      : Gram (symmetric), per layer G <- (I+R)^T G (I+R)
// g_Gt[b]      : Gtmp = G (I+R)
// g_R [p][b]   : R_l ping-pong (zeroed one layer ahead by c1; R[0] by init)
// g_W [p][b]   : W = M^T ping-pong (I included)
// ---------------------------------------------------------------------------
__device__ __align__(16) float g_PB[NLAYER][NHEAD][DP1][DP1];
__device__ __align__(16) float g_QT[NLAYER][NHEAD][DP1][DP1];
__device__ __align__(16) float g_G [BATCH][DP1][DP1];
__device__ __align__(16) float g_Gt[BATCH][DP1][DP1];
__device__ __align__(16) float g_R [2][BATCH][DP1][DP1];
__device__ __align__(16) float g_W [2][BATCH][DP1][DP1];

__device__ __forceinline__ float4 tf32x4(float4 v) {
    v.x = wmma::__float_to_tf32(v.x);  v.y = wmma::__float_to_tf32(v.y);
    v.z = wmma::__float_to_tf32(v.z);  v.w = wmma::__float_to_tf32(v.w);
    return v;
}

// Vector atomic add: one red.global.add.v4.f32 instead of 4 scalar atomics.
__device__ __forceinline__ void red_add_v4(float* ptr, float4 v) {
    asm volatile("red.global.add.v4.f32 [%0], {%1, %2, %3, %4};"
                 :: "l"(ptr), "f"(v.x), "f"(v.y), "f"(v.z), "f"(v.w)
                 : "memory");
}

// ---------------------------------------------------------------------------
__global__ void pad_params_kernel(const float* __restrict__ allparam) {
    int idx = blockIdx.x * blockDim.x + threadIdx.x;
    const int total = NLAYER * NHEAD * DP1 * DP1;
    if (idx >= total) return;
    int bb = idx & 127;
    int a  = (idx >> 7) & 127;
    int h  = (idx >> 14) & 7;
    int l  = idx >> 17;

    float pv = 0.0f, qv = 0.0f;
    if (bb < DSMALL && a < DSMALL) {
        const float* base = allparam
            + ((((size_t)l * NHEAD + h) * 2 + 0) * DSMALL + bb) * DSMALL + a;
        pv = base[0];
        qv = base[DSMALL * DSMALL];
    }
    if (bb == DSMALL && a == DSMALL) pv = 1.0f;

    g_PB[l][h][a][bb] = pv;
    g_QT[l][h][a][bb] = qv;
}

__global__ void init_kernel() {
    int idx = blockIdx.x * blockDim.x + threadIdx.x;   // < 8*128*128
    int j = idx & 127, i = (idx >> 7) & 127, b = idx >> 14;
    g_G[b][i][j] = 0.0f;
    g_R[0][b][i][j] = 0.0f;
    g_W[0][b][i][j] = (i == j) ? 1.0f : 0.0f;
}

// ---------------------------------------------------------------------------
// Gram (tf32 wmma): G[b] += Zslab^T Zslab, slab rows [s*64, s*64+64) ∩ [0,1023)
// grid (8,16), 512 thr. Vector reductions for output accumulate.
// ---------------------------------------------------------------------------
__global__ __launch_bounds__(512)
void gram_kernel(const float* __restrict__ Z) {
    extern __shared__ __align__(16) float dsm[];
    float* Zs = dsm;                 // [64][132]
    float* Cs = dsm + 64 * LD128;    // [128][132]

    const int b = blockIdx.x, s = blockIdx.y;
    const int tid = threadIdx.x;
    const int w = tid >> 5;
    const int rw = (w & 7) * 16;
    const int jt = (w >> 3) * 64;

    const float* Zb = Z + (size_t)b * NP1 * DP1;
    const int m0 = s * 64;

#pragma unroll
    for (int q = 0; q < 4; q++) {
        int f = tid + q * 512;
        int row = f >> 5, c4 = (f & 31) * 4;
        float4 v = make_float4(0.f, 0.f, 0.f, 0.f);
        if (m0 + row < NTOK)
            v = tf32x4(*(const float4*)&Zb[(size_t)(m0 + row) * DP1 + c4]);
        *(float4*)&Zs[row * LD128 + c4] = v;
    }
    __syncthreads();

    wmma::fragment<wmma::accumulator, 16, 16, 8, float> c[4];
#pragma unroll
    for (int j = 0; j < 4; j++) wmma::fill_fragment(c[j], 0.0f);

#pragma unroll
    for (int k0 = 0; k0 < 64; k0 += 8) {
        wmma::fragment<wmma::matrix_a, 16, 16, 8, wmma::precision::tf32,
                       wmma::col_major> a;
        wmma::load_matrix_sync(a, Zs + k0 * LD128 + rw, LD128);
#pragma unroll
        for (int j = 0; j < 4; j++) {
            wmma::fragment<wmma::matrix_b, 16, 16, 8, wmma::precision::tf32,
                           wmma::row_major> bf;
            wmma::load_matrix_sync(bf, Zs + k0 * LD128 + jt + j * 16, LD128);
            wmma::mma_sync(c[j], a, bf, c[j]);
        }
    }
#pragma unroll
    for (int j = 0; j < 4; j++)
        wmma::store_matrix_sync(Cs + rw * LD128 + jt + j * 16, c[j], LD128,
                                wmma::mem_row_major);
    __syncthreads();

    float* Gb = &g_G[b][0][0];
#pragma unroll
    for (int q = 0; q < 8; q++) {
        int f = tid + q * 512;
        int row = f >> 5, c4 = (f & 31) * 4;
        float4 v = *(const float4*)&Cs[row * LD128 + c4];
        red_add_v4(&Gb[row * DP1 + c4], v);
    }
}

// ---------------------------------------------------------------------------
// Fused TR (tf32 wmma, single-stage smem). Block (b, h, s): cols [s*64,+64).
//   Phase 1: Ts = G @ PBslice   (acc regs rounded to tf32 on store)
//   Phase 2: C  = Q @ Ts; R[p][b][:, slice] += C/N  (vector reductions)
// 512 thr; warp w: rows (w&7)*16, cols (w>>3)*32.
// ---------------------------------------------------------------------------
__global__ __launch_bounds__(512)
void tr_kernel(int layer, int p) {
    extern __shared__ __align__(16) float dsm[];
    float* Gs = dsm;                                // [128][132]
    float* Qs = dsm + DP1 * LD128;                  // [128][132]
    float* Ps = dsm + 2 * DP1 * LD128;              // [128][68]
    float* Ts = dsm + 2 * DP1 * LD128 + DP1 * LD64; // [128][68]

    const int b = blockIdx.x, h = blockIdx.y, s = blockIdx.z;
    const int c0 = s * 64;
    const int tid = threadIdx.x;
    const int w = tid >> 5;
    const int rw = (w & 7) * 16;
    const int jt = (w >> 3) * 32;

    const float* Gb = &g_G[b][0][0];
    const float* PB = &g_PB[layer][h][0][0];
    const float* QT = &g_QT[layer][h][0][0];

    // ---- stage everything once ----
#pragma unroll
    for (int q = 0; q < 8; q++) {
        int f = tid + q * 512;
        int row = f >> 5, c4 = (f & 31) * 4;
        *(float4*)&Gs[row * LD128 + c4] =
            tf32x4(*(const float4*)&Gb[row * DP1 + c4]);
        *(float4*)&Qs[row * LD128 + c4] =
            tf32x4(*(const float4*)&QT[row * DP1 + c4]);
    }
#pragma unroll
    for (int q = 0; q < 4; q++) {
        int f = tid + q * 512;
        int row = f >> 4, c4 = (f & 15) * 4;
        *(float4*)&Ps[row * LD64 + c4] =
            tf32x4(*(const float4*)&PB[row * DP1 + c0 + c4]);
    }
    __syncthreads();

    // ---- Phase 1: Ts = G @ Ps ----
    wmma::fragment<wmma::accumulator, 16, 16, 8, float> c0f, c1f;
    wmma::fill_fragment(c0f, 0.0f);
    wmma::fill_fragment(c1f, 0.0f);
#pragma unroll
    for (int k0 = 0; k0 < DP1; k0 += 8) {
        wmma::fragment<wmma::matrix_a, 16, 16, 8, wmma::precision::tf32,
                       wmma::row_major> a;
        wmma::load_matrix_sync(a, Gs + rw * LD128 + k0, LD128);
        wmma::fragment<wmma::matrix_b, 16, 16, 8, wmma::precision::tf32,
                       wmma::row_major> b0, b1;
        wmma::load_matrix_sync(b0, Ps + k0 * LD64 + jt, LD64);
        wmma::load_matrix_sync(b1, Ps + k0 * LD64 + jt + 16, LD64);
        wmma::mma_sync(c0f, a, b0, c0f);
        wmma::mma_sync(c1f, a, b1, c1f);
    }
#pragma unroll
    for (int t = 0; t < c0f.num_elements; t++) {
        c0f.x[t] = wmma::__float_to_tf32(c0f.x[t]);
        c1f.x[t] = wmma::__float_to_tf32(c1f.x[t]);
    }
    wmma::store_matrix_sync(Ts + rw * LD64 + jt, c0f, LD64, wmma::mem_row_major);
    wmma::store_matrix_sync(Ts + rw * LD64 + jt + 16, c1f, LD64, wmma::mem_row_major);
    __syncthreads();

    // ---- Phase 2: C = Q @ Ts ----
    wmma::fill_fragment(c0f, 0.0f);
    wmma::fill_fragment(c1f, 0.0f);
#pragma unroll
    for (int k0 = 0; k0 < DP1; k0 += 8) {
        wmma::fragment<wmma::matrix_a, 16, 16, 8, wmma::precision::tf32,
                       wmma::col_major> a;
        wmma::load_matrix_sync(a, Qs + k0 * LD128 + rw, LD128);
        wmma::fragment<wmma::matrix_b, 16, 16, 8, wmma::precision::tf32,
                       wmma::row_major> b0, b1;
        wmma::load_matrix_sync(b0, Ts + k0 * LD64 + jt, LD64);
        wmma::load_matrix_sync(b1, Ts + k0 * LD64 + jt + 16, LD64);
        wmma::mma_sync(c0f, a, b0, c0f);
        wmma::mma_sync(c1f, a, b1, c1f);
    }
    __syncthreads();   // Ts reads done; reuse Ps for C
    wmma::store_matrix_sync(Ps + rw * LD64 + jt, c0f, LD64, wmma::mem_row_major);
    wmma::store_matrix_sync(Ps + rw * LD64 + jt + 16, c1f, LD64, wmma::mem_row_major);
    __syncthreads();

    // ---- vector reductions into g_R[p][b][:, slice] ----
    const float invN = 1.0f / (float)NTOK;
    float* Rb = &g_R[p][b][0][0];
#pragma unroll
    for (int q = 0; q < 4; q++) {
        int f = tid + q * 512;
        int row = f >> 4, c4 = (f & 15) * 4;
        float4 v = *(const float4*)&Ps[row * LD64 + c4];
        v.x *= invN; v.y *= invN; v.z *= invN; v.w *= invN;
        red_add_v4(&Rb[row * DP1 + c0 + c4], v);
    }
}

// ---------------------------------------------------------------------------
// c1: op0: Gt = G + G@R[p]   op1: W[p^1] = W[p] + R[p]^T @ W[p]
// grid (8,8). 64x64 tile, 4x4 micro. Also zeroes g_R[p^1] for next layer.
// ---------------------------------------------------------------------------
__global__ __launch_bounds__(256) void c1_kernel(int p) {
    const int b = blockIdx.x, d = blockIdx.y;
    const int op = d >> 2, rt = (d >> 1) & 1, ct = d & 1;
    const int i0 = rt * 64, c0 = ct * 64;
    const int tid = threadIdx.x, tx = tid & 15, ty = tid >> 4;
    __shared__ __align__(16) float As[2][16][64];
    __shared__ __align__(16) float Bs[2][16][64];

    const float* Rc = &g_R[p][b][0][0];
    const float* srcA = op ? Rc : &g_G[b][0][0];
    const float* srcB = op ? &g_W[p][b][0][0] : Rc;
    const float* base = op ? &g_W[p][b][0][0] : &g_G[b][0][0];
    float* dst = op ? &g_W[p ^ 1][b][0][0] : &g_Gt[b][0][0];

    const int sr = tid >> 4, sc = (tid & 15) * 4;

    float4 ra, rb;
    ra = *(const float4*)&srcA[(0 + sr) * DP1 + i0 + sc];
    rb = *(const float4*)&srcB[(0 + sr) * DP1 + c0 + sc];
    *(float4*)&As[0][sr][sc] = ra;
    *(float4*)&Bs[0][sr][sc] = rb;
    __syncthreads();

    float acc[4][4];
#pragma unroll
    for (int i = 0; i < 4; i++)
#pragma unroll
        for (int j = 0; j < 4; j++) acc[i][j] = 0.0f;

    for (int t = 0; t < 8; t++) {
        const int cur = t & 1;
        if (t < 7) {
            int k0 = (t + 1) * 16;
            ra = *(const float4*)&srcA[(k0 + sr) * DP1 + i0 + sc];
            rb = *(const float4*)&srcB[(k0 + sr) * DP1 + c0 + sc];
        }
#pragma unroll
        for (int kk = 0; kk < 16; kk++) {
            float4 av = *(const float4*)&As[cur][kk][ty * 4];
            float4 bv = *(const float4*)&Bs[cur][kk][tx * 4];
            float a_[4] = {av.x, av.y, av.z, av.w};
            float b_[4] = {bv.x, bv.y, bv.z, bv.w};
#pragma unroll
            for (int i = 0; i < 4; i++)
#pragma unroll
                for (int j = 0; j < 4; j++) acc[i][j] = fmaf(a_[i], b_[j], acc[i][j]);
        }
        if (t < 7) {
            const int nxt = cur ^ 1;
            *(float4*)&As[nxt][sr][sc] = ra;
            *(float4*)&Bs[nxt][sr][sc] = rb;
            __syncthreads();
        }
    }

#pragma unroll
    for (int i = 0; i < 4; i++) {
        int row = i0 + ty * 4 + i;
        float4 b4 = *(const float4*)&base[row * DP1 + c0 + tx * 4];
        float4 v = make_float4(b4.x + acc[i][0], b4.y + acc[i][1],
                               b4.z + acc[i][2], b4.w + acc[i][3]);
        *(float4*)&dst[row * DP1 + c0 + tx * 4] = v;
    }

    // zero next-parity R for the next layer's tr reductions
    {
        float* Rn = &g_R[p ^ 1][0][0][0];
        int blk = b * 8 + d;              // 0..63
#pragma unroll
        for (int k = 0; k < 8; k++)
            Rn[blk * 2048 + k * 256 + tid] = 0.0f;
    }
}

// ---------------------------------------------------------------------------
// c2: G = Gt + R[p]^T @ Gt.  grid (8,4).
// ---------------------------------------------------------------------------
__global__ __launch_bounds__(256) void c2_kernel(int p) {
    const int b = blockIdx.x, d = blockIdx.y;
    const int rt = d >> 1, ct = d & 1;
    const int i0 = rt * 64, c0 = ct * 64;
    const int tid = threadIdx.x, tx = tid & 15, ty = tid >> 4;
    __shared__ __align__(16) float As[2][16][64];
    __shared__ __align__(16) float Bs[2][16][64];

    const float* srcA = &g_R[p][b][0][0];
    const float* srcB = &g_Gt[b][0][0];

    const int sr = tid >> 4, sc = (tid & 15) * 4;

    float4 ra, rb;
    ra = *(const float4*)&srcA[(0 + sr) * DP1 + i0 + sc];
    rb = *(const float4*)&srcB[(0 + sr) * DP1 + c0 + sc];
    *(float4*)&As[0][sr][sc] = ra;
    *(float4*)&Bs[0][sr][sc] = rb;
    __syncthreads();

    float acc[4][4];
#pragma unroll
    for (int i = 0; i < 4; i++)
#pragma unroll
        for (int j = 0; j < 4; j++) acc[i][j] = 0.0f;

    for (int t = 0; t < 8; t++) {
        const int cur = t & 1;
        if (t < 7) {
            int k0 = (t + 1) * 16;
            ra = *(const float4*)&srcA[(k0 + sr) * DP1 + i0 + sc];
            rb = *(const float4*)&srcB[(k0 + sr) * DP1 + c0 + sc];
        }
#pragma unroll
        for (int kk = 0; kk < 16; kk++) {
            float4 av = *(const float4*)&As[cur][kk][ty * 4];
            float4 bv = *(const float4*)&Bs[cur][kk][tx * 4];
            float a_[4] = {av.x, av.y, av.z, av.w};
            float b_[4] = {bv.x, bv.y, bv.z, bv.w};
#pragma unroll
            for (int i = 0; i < 4; i++)
#pragma unroll
                for (int j = 0; j < 4; j++) acc[i][j] = fmaf(a_[i], b_[j], acc[i][j]);
        }
        if (t < 7) {
            const int nxt = cur ^ 1;
            *(float4*)&As[nxt][sr][sc] = ra;
            *(float4*)&Bs[nxt][sr][sc] = rb;
            __syncthreads();
        }
    }

    float* Gb = &g_G[b][0][0];
    const float* Gt = &g_Gt[b][0][0];
#pragma unroll
    for (int i = 0; i < 4; i++) {
        int row = i0 + ty * 4 + i;
        float4 b4 = *(const float4*)&Gt[row * DP1 + c0 + tx * 4];
        float4 v = make_float4(b4.x + acc[i][0], b4.y + acc[i][1],
                               b4.z + acc[i][2], b4.w + acc[i][3]);
        *(float4*)&Gb[row * DP1 + c0 + tx * 4] = v;
    }
}

// ---------------------------------------------------------------------------
// Final (tf32 wmma on correction): Zout = Zin + Zin @ E^T, E = W[pw] - I.
// grid (8,8), 512 thr.
// ---------------------------------------------------------------------------
__global__ __launch_bounds__(512)
void final_kernel(const float* __restrict__ Zin, float* __restrict__ Zout,
                  int pw) {
    extern __shared__ __align__(16) float dsm[];
    float* Zs = dsm;                 // [128][132]
    float* Es = dsm + DP1 * LD128;   // [128][132]

    const int b = blockIdx.x, rt = blockIdx.y;
    const int n0 = rt * 128;
    const int tid = threadIdx.x;
    const int w = tid >> 5;
    const int rw = (w & 7) * 16;
    const int jt = (w >> 3) * 64;

    const float* Zb = Zin + (size_t)b * NP1 * DP1;
    float* Zo = Zout + (size_t)b * NP1 * DP1;
    const float* Wb = &g_W[pw][b][0][0];

#pragma unroll
    for (int q = 0; q < 8; q++) {
        int f = tid + q * 512;
        int row = f >> 5, c4 = (f & 31) * 4;
        *(float4*)&Zs[row * LD128 + c4] =
            tf32x4(*(const float4*)&Zb[(size_t)(n0 + row) * DP1 + c4]);
        float4 e = *(const float4*)&Wb[row * DP1 + c4];
        if (row >= c4 && row < c4 + 4) {
            if (row == c4)          e.x -= 1.0f;
            else if (row == c4 + 1) e.y -= 1.0f;
            else if (row == c4 + 2) e.z -= 1.0f;
            else                    e.w -= 1.0f;
        }
        *(float4*)&Es[row * LD128 + c4] = tf32x4(e);
    }
    __syncthreads();

    wmma::fragment<wmma::accumulator, 16, 16, 8, float> c[4];
#pragma unroll
    for (int j = 0; j < 4; j++) wmma::fill_fragment(c[j], 0.0f);

#pragma unroll
    for (int k0 = 0; k0 < DP1; k0 += 8) {
        wmma::fragment<wmma::matrix_a, 16, 16, 8, wmma::precision::tf32,
                       wmma::row_major> a;
        wmma::load_matrix_sync(a, Zs + rw * LD128 + k0, LD128);
#pragma unroll
        for (int j = 0; j < 4; j++) {
            wmma::fragment<wmma::matrix_b, 16, 16, 8, wmma::precision::tf32,
                           wmma::col_major> bf;
            wmma::load_matrix_sync(bf, Es + (jt + j * 16) * LD128 + k0, LD128);
            wmma::mma_sync(c[j], a, bf, c[j]);
        }
    }
    __syncthreads();
#pragma unroll
    for (int j = 0; j < 4; j++)
        wmma::store_matrix_sync(Zs + rw * LD128 + jt + j * 16, c[j], LD128,
                                wmma::mem_row_major);
    __syncthreads();

#pragma unroll
    for (int q = 0; q < 8; q++) {
        int f = tid + q * 512;
        int row = f >> 5, c4 = (f & 31) * 4;
        size_t off = (size_t)(n0 + row) * DP1 + c4;
        float4 z = *(const float4*)&Zb[off];
        float4 cc = *(const float4*)&Zs[row * LD128 + c4];
        *(float4*)&Zo[off] =
            make_float4(z.x + cc.x, z.y + cc.y, z.z + cc.z, z.w + cc.w);
    }
}

// ---------------------------------------------------------------------------
extern "C" void kernel_launch(void* const* d_in, const int* in_sizes, int n_in,
                              void* d_out, int out_size) {
    const float* Z_in     = (const float*)d_in[0];
    const float* allparam = (const float*)d_in[1];
    float* Z_out = (float*)d_out;

    cudaFuncSetAttribute(tr_kernel,
                         cudaFuncAttributeMaxDynamicSharedMemorySize, TR_SMEM);
    cudaFuncSetAttribute(gram_kernel,
                         cudaFuncAttributeMaxDynamicSharedMemorySize, GRAM_SMEM);
    cudaFuncSetAttribute(final_kernel,
                         cudaFuncAttributeMaxDynamicSharedMemorySize, FIN_SMEM);

    pad_params_kernel<<<(NLAYER * NHEAD * DP1 * DP1 + 255) / 256, 256>>>(allparam);
    init_kernel<<<(BATCH * DP1 * DP1 + 255) / 256, 256>>>();
    gram_kernel<<<dim3(BATCH, 16), 512, GRAM_SMEM>>>(Z_in);

    for (int l = 0; l < NLAYER; l++) {
        int p = l & 1;
        tr_kernel<<<dim3(BATCH, NHEAD, 2), 512, TR_SMEM>>>(l, p);
        c1_kernel<<<dim3(BATCH, 8), 256>>>(p);
        if (l < NLAYER - 1)
            c2_kernel<<<dim3(BATCH, 4), 256>>>(p);
    }

    final_kernel<<<dim3(BATCH, 8), 512, FIN_SMEM>>>(Z_in, Z_out, NLAYER & 1);
}